// round 5
// baseline (speedup 1.0000x reference)
#include <cuda_runtime.h>
#include <cuda_fp16.h>
#include <stdint.h>

// Problem constants
#define SDIM 4096
#define ADIM 1024
#define DDIM 5
#define HDIM 64

// ---------------- low-level helpers ----------------

__device__ __forceinline__ float tanh_f32(float x) {
    float y;
    asm("tanh.approx.f32 %0, %1;" : "=f"(y) : "f"(x));
    return y;
}

__device__ __forceinline__ unsigned tanh_f16x2(unsigned x) {
    unsigned y;
    asm("tanh.approx.f16x2 %0, %1;" : "=r"(y) : "r"(x));
    return y;
}

// pack: result.lo = lo_val, result.hi = hi_val  (cvt.rn.f16x2.f32 d,a,b -> d.hi=a, d.lo=b)
__device__ __forceinline__ unsigned pack_f16x2(float hi_val, float lo_val) {
    unsigned d;
    asm("cvt.rn.f16x2.f32 %0, %1, %2;" : "=r"(d) : "f"(hi_val), "f"(lo_val));
    return d;
}

__device__ __forceinline__ unsigned pack_halves(__half lo, __half hi) {
    return ((unsigned)__half_as_ushort(hi) << 16) | (unsigned)__half_as_ushort(lo);
}

// fp16 two-term split of (x0,x1): hi = rn(x), lo = rn(x - f32(hi)); packed k-order (x0 in low half)
__device__ __forceinline__ void split2(float x0, float x1, unsigned& hi, unsigned& lo) {
    __half h0 = __float2half_rn(x0);
    __half h1 = __float2half_rn(x1);
    float r0 = x0 - __half2float(h0);
    float r1 = x1 - __half2float(h1);
    hi = pack_halves(h0, h1);
    lo = pack_halves(__float2half_rn(r0), __float2half_rn(r1));
}

__device__ __forceinline__ void mma16(float& c0, float& c1, float& c2, float& c3,
                                      unsigned a0, unsigned a1, unsigned a2, unsigned a3,
                                      unsigned b0, unsigned b1) {
    asm("mma.sync.aligned.m16n8k16.row.col.f32.f16.f16.f32 "
        "{%0,%1,%2,%3},{%4,%5,%6,%7},{%8,%9},{%0,%1,%2,%3};"
        : "+f"(c0), "+f"(c1), "+f"(c2), "+f"(c3)
        : "r"(a0), "r"(a1), "r"(a2), "r"(a3), "r"(b0), "r"(b1));
}

__device__ __forceinline__ void mma8(float& c0, float& c1, float& c2, float& c3,
                                     unsigned a0, unsigned a1, unsigned b0) {
    asm("mma.sync.aligned.m16n8k8.row.col.f32.f16.f16.f32 "
        "{%0,%1,%2,%3},{%4,%5},{%6},{%0,%1,%2,%3};"
        : "+f"(c0), "+f"(c1), "+f"(c2), "+f"(c3)
        : "r"(a0), "r"(a1), "r"(b0));
}

// ---------------- kernel ----------------
// Grid: (ADIM, 4). Block: 256 threads (8 warps).
// Block (a, y) handles atom a, rows [y*1024, y*1024+1024).
// Each warp processes 64 rows per iteration, 2 iterations.

__global__ __launch_bounds__(256, 1)
void nn_grouped_mlp_kernel(const float* __restrict__ g,
                           const float* __restrict__ W1,
                           const float* __restrict__ b1,
                           const float* __restrict__ W2,
                           const float* __restrict__ b2,
                           const float* __restrict__ W3,
                           const float* __restrict__ b3,
                           float* __restrict__ out) {
    // smem: pre-swizzled B-fragments (fp16 hi/lo split)
    __shared__ uint4 w2f[1024];  // [kstep(4)][ntile(8)][lane(32)] : {hi_b0,hi_b1,lo_b0,lo_b1}  16 KB
    __shared__ uint2 w1f[256];   // [ntile(8)][lane(32)]           : {hi_b0, lo_b0}             2 KB
    __shared__ uint4 w3f[128];   // [kstep(4)][lane(32)]           : {hi_b0,hi_b1,lo_b0,lo_b1}  2 KB

    const int a    = blockIdx.x;
    const int tid  = threadIdx.x;
    const int lane = tid & 31;
    const int warp = tid >> 5;
    const int kp   = lane & 3;   // k-pair index within fragments
    const int row8 = lane >> 2;  // row within 8-row group / n-col selector

    // ---- preprocess W2 into split B-fragments ----
    {
        const float* W2a = W2 + a * (HDIM * HDIM);
        #pragma unroll
        for (int c = tid; c < 1024; c += 256) {
            int l    = c & 31;
            int lkp  = l & 3;
            int colg = (((c >> 5) & 7) << 3) + (l >> 2);  // 8*ntile + lane/4
            int k0   = ((c >> 8) << 4) + (lkp << 1);      // 16*kstep + 2*kp
            float f0 = W2a[(k0    ) * HDIM + colg];
            float f1 = W2a[(k0 + 1) * HDIM + colg];
            float f2 = W2a[(k0 + 8) * HDIM + colg];
            float f3 = W2a[(k0 + 9) * HDIM + colg];
            uint4 q;
            split2(f0, f1, q.x, q.z);
            split2(f2, f3, q.y, q.w);
            w2f[c] = q;
        }
    }
    // ---- preprocess W1 (K padded 5 -> 8) ----
    if (tid < 256) {
        const float* W1a = W1 + a * (DDIM * HDIM);
        int l    = tid & 31;
        int lkp  = l & 3;
        int colg = ((tid >> 5) << 3) + (l >> 2);
        int k0 = 2 * lkp, k1 = 2 * lkp + 1;
        float f0 = (k0 < DDIM) ? W1a[k0 * HDIM + colg] : 0.0f;
        float f1 = (k1 < DDIM) ? W1a[k1 * HDIM + colg] : 0.0f;
        uint2 q;
        split2(f0, f1, q.x, q.y);
        w1f[tid] = q;
    }
    // ---- preprocess W3 (n=8 tile, only col 0 real) ----
    if (tid < 128) {
        const float* W3a = W3 + a * HDIM;
        int l    = tid & 31;
        int lkp  = l & 3;
        int colg = l >> 2;
        int k0   = ((tid >> 5) << 4) + (lkp << 1);
        float f0 = 0.f, f1 = 0.f, f2 = 0.f, f3 = 0.f;
        if (colg == 0) {
            f0 = W3a[k0];
            f1 = W3a[k0 + 1];
            f2 = W3a[k0 + 8];
            f3 = W3a[k0 + 9];
        }
        uint4 q;
        split2(f0, f1, q.x, q.z);
        split2(f2, f3, q.y, q.w);
        w3f[tid] = q;
    }

    // ---- per-thread bias registers (exact fp32, folded via accumulator init) ----
    float bb1[16], bb2[16];
    {
        const float* b1a = b1 + a * HDIM;
        const float* b2a = b2 + a * HDIM;
        #pragma unroll
        for (int n = 0; n < 8; ++n) {
            int col = (n << 3) + (kp << 1);
            bb1[2 * n]     = b1a[col];
            bb1[2 * n + 1] = b1a[col + 1];
            bb2[2 * n]     = b2a[col];
            bb2[2 * n + 1] = b2a[col + 1];
        }
    }
    const float b3v = b3[a];

    __syncthreads();

    const int sbase = blockIdx.y * 1024;

    #pragma unroll
    for (int it = 0; it < 2; ++it) {
        const int sb = sbase + it * 512 + warp * 64;  // first row of this warp's 64-row chunk

        // ================= Phase A: GEMM1 (split fp16 MMA) + tanh(f32) + pack h1 ============
        // h1p[rt][4*ks + {0..3}] are directly the GEMM2 A-fragment registers.
        unsigned h1p[4][16];
        #pragma unroll
        for (int rt = 0; rt < 4; ++rt) {
            const int r0 = sb + rt * 16 + row8;  // rows r0 and r0+8
            const float* g0 = g + ((size_t)r0 * ADIM + a) * DDIM;
            const float* g1 = g0 + (size_t)8 * ADIM * DDIM;
            const int k0 = 2 * kp, k1 = 2 * kp + 1;
            float x00 = (k0 < DDIM) ? g0[k0] : 0.0f;
            float x01 = (k1 < DDIM) ? g0[k1] : 0.0f;
            float x10 = (k0 < DDIM) ? g1[k0] : 0.0f;
            float x11 = (k1 < DDIM) ? g1[k1] : 0.0f;
            unsigned ah0, al0, ah1, al1;
            split2(x00, x01, ah0, al0);
            split2(x10, x11, ah1, al1);

            #pragma unroll
            for (int n = 0; n < 8; ++n) {
                uint2 wb = w1f[n * 32 + lane];
                float c0 = bb1[2 * n], c1 = bb1[2 * n + 1];
                float c2 = c0, c3 = c1;
                mma8(c0, c1, c2, c3, ah0, ah1, wb.x);  // hi*hi
                mma8(c0, c1, c2, c3, al0, al1, wb.x);  // lo*hi
                mma8(c0, c1, c2, c3, ah0, ah1, wb.y);  // hi*lo
                c0 = tanh_f32(c0);
                c1 = tanh_f32(c1);
                c2 = tanh_f32(c2);
                c3 = tanh_f32(c3);
                h1p[rt][2 * n]     = pack_f16x2(c1, c0);  // row r0   (k even in low half)
                h1p[rt][2 * n + 1] = pack_f16x2(c3, c2);  // row r0+8
            }
        }

        // ================= Phase B: GEMM2 (h1 x splitW2) + tanh(f16x2) + GEMM3 (splitW3) ====
        float ea[4][4];
        #pragma unroll
        for (int rt = 0; rt < 4; ++rt) {
            ea[rt][0] = (kp == 0) ? b3v : 0.0f;
            ea[rt][1] = 0.0f;
            ea[rt][2] = ea[rt][0];
            ea[rt][3] = 0.0f;
        }

        #pragma unroll
        for (int p = 0; p < 4; ++p) {  // ntile pair (2p, 2p+1) == GEMM3 k-step p
            float c[4][8];
            #pragma unroll
            for (int rt = 0; rt < 4; ++rt) {
                c[rt][0] = bb2[4 * p];     c[rt][1] = bb2[4 * p + 1];
                c[rt][2] = c[rt][0];       c[rt][3] = c[rt][1];
                c[rt][4] = bb2[4 * p + 2]; c[rt][5] = bb2[4 * p + 3];
                c[rt][6] = c[rt][4];       c[rt][7] = c[rt][5];
            }
            #pragma unroll
            for (int ks = 0; ks < 4; ++ks) {
                uint4 q0 = w2f[(ks * 8 + 2 * p) * 32 + lane];
                uint4 q1 = w2f[(ks * 8 + 2 * p + 1) * 32 + lane];
                #pragma unroll
                for (int rt = 0; rt < 4; ++rt) {
                    unsigned a0 = h1p[rt][4 * ks], a1 = h1p[rt][4 * ks + 1];
                    unsigned a2 = h1p[rt][4 * ks + 2], a3 = h1p[rt][4 * ks + 3];
                    mma16(c[rt][0], c[rt][1], c[rt][2], c[rt][3], a0, a1, a2, a3, q0.x, q0.y);
                    mma16(c[rt][0], c[rt][1], c[rt][2], c[rt][3], a0, a1, a2, a3, q0.z, q0.w);
                    mma16(c[rt][4], c[rt][5], c[rt][6], c[rt][7], a0, a1, a2, a3, q1.x, q1.y);
                    mma16(c[rt][4], c[rt][5], c[rt][6], c[rt][7], a0, a1, a2, a3, q1.z, q1.w);
                }
            }
            // tanh(h2) in f16x2; packed accs feed GEMM3 A-fragments directly
            uint4 q3 = w3f[p * 32 + lane];
            #pragma unroll
            for (int rt = 0; rt < 4; ++rt) {
                unsigned u0 = tanh_f16x2(pack_f16x2(c[rt][1], c[rt][0]));
                unsigned u1 = tanh_f16x2(pack_f16x2(c[rt][3], c[rt][2]));
                unsigned u2 = tanh_f16x2(pack_f16x2(c[rt][5], c[rt][4]));
                unsigned u3 = tanh_f16x2(pack_f16x2(c[rt][7], c[rt][6]));
                mma16(ea[rt][0], ea[rt][1], ea[rt][2], ea[rt][3], u0, u1, u2, u3, q3.x, q3.y);
                mma16(ea[rt][0], ea[rt][1], ea[rt][2], ea[rt][3], u0, u1, u2, u3, q3.z, q3.w);
            }
        }

        // ================= store e (col 0 of GEMM3 result lives in lanes with kp==0) =======
        if (kp == 0) {
            #pragma unroll
            for (int rt = 0; rt < 4; ++rt) {
                int r0 = sb + rt * 16 + row8;
                out[(size_t)r0 * ADIM + a]       = ea[rt][0];
                out[(size_t)(r0 + 8) * ADIM + a] = ea[rt][2];
            }
        }
    }
}

extern "C" void kernel_launch(void* const* d_in, const int* in_sizes, int n_in,
                              void* d_out, int out_size) {
    const float* g  = (const float*)d_in[0];
    const float* W1 = (const float*)d_in[1];
    const float* b1 = (const float*)d_in[2];
    const float* W2 = (const float*)d_in[3];
    const float* b2 = (const float*)d_in[4];
    const float* W3 = (const float*)d_in[5];
    const float* b3 = (const float*)d_in[6];
    float* out = (float*)d_out;

    dim3 grid(ADIM, 4);
    dim3 block(256);
    nn_grouped_mlp_kernel<<<grid, block>>>(g, W1, b1, W2, b2, W3, b3, out);
}